// round 1
// baseline (speedup 1.0000x reference)
#include <cuda_runtime.h>
#include <math.h>

// ---------------------------------------------------------------------------
// Problem constants
// ---------------------------------------------------------------------------
#define NQ        16          // batch of queries
#define DIM       1024        // C*L2 flattened dim
#define NDB       400000      // database rows
#define EPSV      1e-8f

// Main kernel config
#define T         128                     // threads per block
#define RPT       2                       // rows per thread
#define RB        (T * RPT)               // 256 rows per block
#define KT        16                      // K-tile (floats)
#define KSTRIDE   20                      // padded smem row stride (conflict-free LDS.128)
#define NTILES    (DIM / KT)              // 64
#define NBLK      ((NDB + RB - 1) / RB)   // 1563
#define STAGE_FLOATS (RB * KSTRIDE)       // 5120 floats per pipeline stage
#define SMEM_FLOATS  (NQ * DIM + 2 * STAGE_FLOATS)   // 16384 + 10240 = 26624
#define SMEM_BYTES   (SMEM_FLOATS * 4)               // 106496 B -> 2 blocks/SM

typedef unsigned long long u64;

// ---------------------------------------------------------------------------
// Device scratch (no allocations allowed)
// ---------------------------------------------------------------------------
__device__ float g_qn[NQ * DIM];         // normalized queries
__device__ u64   g_pkey[NBLK * NQ];      // per-block packed (sim,idx) max
__device__ float g_psum[NBLK * NQ];      // per-block sim sums

// ---------------------------------------------------------------------------
// f32x2 packed helpers (sm_103a FFMA2 path)
// ---------------------------------------------------------------------------
__device__ __forceinline__ void ffma2(u64 &d, u64 a, u64 b) {
    asm("fma.rn.f32x2 %0, %1, %2, %0;" : "+l"(d) : "l"(a), "l"(b));
}
__device__ __forceinline__ float2 unpack2(u64 v) {
    float2 f;
    asm("mov.b64 {%0,%1}, %2;" : "=f"(f.x), "=f"(f.y) : "l"(v));
    return f;
}

// Order-preserving float -> uint mapping, packed with (~idx) so that
// larger sim wins, and ties prefer the LOWER index (matches jnp.argmax).
__device__ __forceinline__ u64 pack_key(float f, int idx) {
    unsigned b = __float_as_uint(f);
    unsigned o = (b & 0x80000000u) ? ~b : (b | 0x80000000u);
    return ((u64)o << 32) | (unsigned)(~(unsigned)idx);
}

// ---------------------------------------------------------------------------
// Kernel 1: normalize queries  (16 blocks x 256 threads)
// ---------------------------------------------------------------------------
__global__ void qnorm_kernel(const float* __restrict__ q) {
    const int b = blockIdx.x;
    const int t = threadIdx.x;                 // 256 threads, 4 floats each
    const float* row = q + b * DIM;
    float4 v = *(const float4*)(row + t * 4);
    float s = v.x * v.x + v.y * v.y + v.z * v.z + v.w * v.w;

    __shared__ float red[8];
    __shared__ float invn;
    #pragma unroll
    for (int o = 16; o; o >>= 1) s += __shfl_xor_sync(0xFFFFFFFFu, s, o);
    if ((t & 31) == 0) red[t >> 5] = s;
    __syncthreads();
    if (t == 0) {
        float tot = 0.f;
        #pragma unroll
        for (int i = 0; i < 8; i++) tot += red[i];
        invn = 1.f / (sqrtf(tot) + EPSV);
    }
    __syncthreads();
    float iv = invn;
    float4 o4 = make_float4(v.x * iv, v.y * iv, v.z * iv, v.w * iv);
    *(float4*)(g_qn + b * DIM + t * 4) = o4;
}

// ---------------------------------------------------------------------------
// Kernel 2: main similarity kernel
//   1563 blocks x 128 threads, 256 rows/block (2 rows/thread),
//   2-stage cp.async pipeline over K tiles of 16, FFMA2 inner loop.
// ---------------------------------------------------------------------------
__device__ __forceinline__ void issue_tile(const float* __restrict__ db,
                                           float* db_s, int rowBase, int tile,
                                           int t) {
    const int kB = tile * KT;
    const unsigned sb =
        (unsigned)__cvta_generic_to_shared(db_s + (tile & 1) * STAGE_FLOATS);
    #pragma unroll
    for (int i = 0; i < 8; i++) {
        int idx = t + i * T;            // 0..1023 float4 slots (256 rows x 4)
        int row = idx >> 2;
        int ch  = idx & 3;
        long long grow = rowBase + row;
        if (grow > NDB - 1) grow = NDB - 1;   // clamp (excluded in epilogue)
        const float* src = db + grow * (long long)DIM + kB + ch * 4;
        unsigned dst = sb + (unsigned)((row * KSTRIDE + ch * 4) * 4);
        asm volatile("cp.async.cg.shared.global [%0], [%1], 16;"
                     :: "r"(dst), "l"(src));
    }
    asm volatile("cp.async.commit_group;");
}

__global__ void __launch_bounds__(T, 2)
sim_kernel(const float* __restrict__ db) {
    extern __shared__ float smem[];
    float* q_s  = smem;                 // NQ*DIM
    float* db_s = smem + NQ * DIM;      // 2 * STAGE_FLOATS

    const int t = threadIdx.x;
    const int rowBase = blockIdx.x * RB;
    const int r0 = rowBase + t;
    const int r1 = rowBase + T + t;

    // Load normalized queries into shared (16384 floats / 128 thr = 32 float4)
    #pragma unroll
    for (int i = 0; i < 32; i++) {
        int idx = t + i * T;
        *(float4*)&q_s[idx * 4] = *(const float4*)&g_qn[idx * 4];
    }

    // Accumulators: f32x2 holds (even-k partial, odd-k partial)
    u64 acc0[NQ], acc1[NQ];
    u64 nrm0 = 0ull, nrm1 = 0ull;
    #pragma unroll
    for (int q = 0; q < NQ; q++) { acc0[q] = 0ull; acc1[q] = 0ull; }

    issue_tile(db, db_s, rowBase, 0, t);
    issue_tile(db, db_s, rowBase, 1, t);

    for (int tt = 0; tt < NTILES; ++tt) {
        if (tt + 1 < NTILES) asm volatile("cp.async.wait_group 1;");
        else                 asm volatile("cp.async.wait_group 0;");
        __syncthreads();

        const float* p0 = db_s + (tt & 1) * STAGE_FLOATS + t * KSTRIDE;
        const float* p1 = p0 + T * KSTRIDE;
        const float* qb = q_s + tt * KT;

        #pragma unroll
        for (int kk = 0; kk < KT; kk += 4) {
            longlong2 dv0 = *(const longlong2*)(p0 + kk);
            longlong2 dv1 = *(const longlong2*)(p1 + kk);
            u64 a0 = (u64)dv0.x, a1 = (u64)dv0.y;
            u64 b0 = (u64)dv1.x, b1 = (u64)dv1.y;
            ffma2(nrm0, a0, a0); ffma2(nrm0, a1, a1);
            ffma2(nrm1, b0, b0); ffma2(nrm1, b1, b1);
            #pragma unroll
            for (int q = 0; q < NQ; q++) {
                longlong2 qv = *(const longlong2*)(qb + q * DIM + kk);
                u64 q0 = (u64)qv.x, q1 = (u64)qv.y;
                ffma2(acc0[q], a0, q0); ffma2(acc0[q], a1, q1);
                ffma2(acc1[q], b0, q0); ffma2(acc1[q], b1, q1);
            }
        }
        __syncthreads();
        if (tt + 2 < NTILES) issue_tile(db, db_s, rowBase, tt + 2, t);
    }

    // ---- epilogue: sims, per-thread best/sum, block reduction ----
    float2 n0 = unpack2(nrm0), n1 = unpack2(nrm1);
    float inv0 = 1.f / (sqrtf(n0.x + n0.y) + EPSV);
    float inv1 = 1.f / (sqrtf(n1.x + n1.y) + EPSV);
    const bool v0 = (r0 < NDB), v1 = (r1 < NDB);

    // Reuse db staging smem for reduction scratch (24.5 KB of 40 KB)
    u64*   rkey = (u64*)db_s;
    float* rsum = (float*)(rkey + NQ * T);

    #pragma unroll
    for (int q = 0; q < NQ; q++) {
        float2 a  = unpack2(acc0[q]);
        float2 bb = unpack2(acc1[q]);
        float s0 = (a.x + a.y) * inv0;
        float s1 = (bb.x + bb.y) * inv1;
        u64 k0 = v0 ? pack_key(s0, r0) : 0ull;
        u64 k1 = v1 ? pack_key(s1, r1) : 0ull;
        u64 kb = (k1 > k0) ? k1 : k0;
        float sm = (v0 ? s0 : 0.f) + (v1 ? s1 : 0.f);
        rkey[q * T + t] = kb;
        rsum[q * T + t] = sm;
    }
    __syncthreads();

    const int lane = t & 31, w = t >> 5;       // 4 warps, 4 queries each
    #pragma unroll
    for (int j = 0; j < 4; j++) {
        int q = w * 4 + j;
        u64 kb  = rkey[q * T + lane];
        float sm = rsum[q * T + lane];
        #pragma unroll
        for (int i = 1; i < 4; i++) {
            u64 kk2 = rkey[q * T + lane + i * 32];
            if (kk2 > kb) kb = kk2;
            sm += rsum[q * T + lane + i * 32];
        }
        #pragma unroll
        for (int o = 16; o; o >>= 1) {
            u64   ok = __shfl_xor_sync(0xFFFFFFFFu, kb, o);
            float os = __shfl_xor_sync(0xFFFFFFFFu, sm, o);
            if (ok > kb) kb = ok;
            sm += os;
        }
        if (lane == 0) {
            g_pkey[(size_t)blockIdx.x * NQ + q] = kb;
            g_psum[(size_t)blockIdx.x * NQ + q] = sm;
        }
    }
}

// ---------------------------------------------------------------------------
// Kernel 3: finalize — reduce 1563 partials, emit 49-float output
//   out[0:16) unit_sim, [16:32) avg_sim, [32:48) top_cls, [48] accuracy
// ---------------------------------------------------------------------------
__global__ void finalize_kernel(const int* __restrict__ db_classes,
                                const int* __restrict__ y,
                                float* __restrict__ out) {
    const int t = threadIdx.x;        // 256
    const int q = t >> 4, sub = t & 15;

    u64 kb = 0ull; float sm = 0.f;
    for (int i = sub; i < NBLK; i += 16) {
        u64 k = g_pkey[(size_t)i * NQ + q];
        if (k > kb) kb = k;
        sm += g_psum[(size_t)i * NQ + q];
    }
    #pragma unroll
    for (int o = 8; o; o >>= 1) {
        u64   ok = __shfl_down_sync(0xFFFFFFFFu, kb, o, 16);
        float os = __shfl_down_sync(0xFFFFFFFFu, sm, o, 16);
        if (ok > kb) kb = ok;
        sm += os;
    }

    __shared__ u64   skey[NQ];
    __shared__ float ssum[NQ];
    __shared__ int   scls[NQ];
    if (sub == 0) { skey[q] = kb; ssum[q] = sm; }
    __syncthreads();

    if (t < NQ) {
        u64 k = skey[t];
        unsigned idx = ~((unsigned)k);
        unsigned o   = (unsigned)(k >> 32);
        unsigned fb  = (o & 0x80000000u) ? (o & 0x7FFFFFFFu) : ~o;
        float mx = __uint_as_float(fb);
        int cls = db_classes[idx];
        out[t]           = mx;
        out[NQ + t]      = ssum[t] / (float)NDB;
        out[2 * NQ + t]  = (float)cls;
        scls[t] = cls;
    }
    __syncthreads();
    if (t == 0) {
        int c = 0;
        #pragma unroll
        for (int i = 0; i < NQ; i++) c += (scls[i] == y[i]) ? 1 : 0;
        out[3 * NQ] = (float)c / (float)NQ;
    }
}

// ---------------------------------------------------------------------------
// kernel_launch
// ---------------------------------------------------------------------------
extern "C" void kernel_launch(void* const* d_in, const int* in_sizes, int n_in,
                              void* d_out, int out_size) {
    const float* queries    = (const float*)d_in[0];   // [16,32,32]
    const float* database   = (const float*)d_in[1];   // [400000,32,32]
    const int*   db_classes = (const int*)d_in[2];     // [400000]
    const int*   y          = (const int*)d_in[3];     // [16]
    float* out = (float*)d_out;                        // 49 floats

    cudaFuncSetAttribute(sim_kernel,
                         cudaFuncAttributeMaxDynamicSharedMemorySize,
                         SMEM_BYTES);

    qnorm_kernel<<<NQ, 256>>>(queries);
    sim_kernel<<<NBLK, T, SMEM_BYTES>>>(database);
    finalize_kernel<<<1, 256>>>(db_classes, y, out);
}

// round 3
// speedup vs baseline: 1.5036x; 1.5036x over previous
#include <cuda_runtime.h>
#include <cuda_bf16.h>
#include <math.h>

// ---------------------------------------------------------------------------
// Problem constants
// ---------------------------------------------------------------------------
#define NQ      16
#define DIM     1024
#define NDB     400000
#define RB      256                       // rows per CTA (8 warps x 32 rows)
#define NBLK    ((NDB + RB - 1) / RB)     // 1563
#define NCHUNK  (DIM / 16)                // 64 k16 chunks
#define EPSV    1e-8f

// Padded query row: 1024 + 16 bf16 -> stride 2080 bytes (conflict-free LDS.64)
#define QSTRIDE_E  1040
#define QSTRIDE_B  2080
#define QMAT_B     (NQ * QSTRIDE_B)       // 33280 bytes per matrix (hi or lo)
#define QTOT_B     (2 * QMAT_B)           // 66560
#define SCRATCH_B  2048
#define SMEM_TOTAL (QTOT_B + SCRATCH_B)

typedef unsigned int       u32;
typedef unsigned long long u64;

// ---------------------------------------------------------------------------
// Device scratch
// ---------------------------------------------------------------------------
__device__ __align__(16) char g_qB[QTOT_B];   // [hi|lo] padded bf16 queries
__device__ u64   g_pkey[NBLK * NQ];
__device__ float g_psum[NBLK * NQ];

// ---------------------------------------------------------------------------
// Helpers
// ---------------------------------------------------------------------------
__device__ __forceinline__ u32 cvtpack(float hi, float lo) {
    // returns bf16x2: low half = round(lo), high half = round(hi)
    __nv_bfloat162 h = __floats2bfloat162_rn(lo, hi);
    return *(u32*)&h;
}
__device__ __forceinline__ float lo2f(u32 p) { return __uint_as_float(p << 16); }
__device__ __forceinline__ float hi2f(u32 p) { return __uint_as_float(p & 0xFFFF0000u); }

__device__ __forceinline__ void mma16816(float* d, const u32* a, const u32* b) {
    asm volatile(
        "mma.sync.aligned.m16n8k16.row.col.f32.bf16.bf16.f32 "
        "{%0,%1,%2,%3}, {%4,%5,%6,%7}, {%8,%9}, {%0,%1,%2,%3};"
        : "+f"(d[0]), "+f"(d[1]), "+f"(d[2]), "+f"(d[3])
        : "r"(a[0]), "r"(a[1]), "r"(a[2]), "r"(a[3]), "r"(b[0]), "r"(b[1]));
}

__device__ __forceinline__ u64 pack_key(float f, int idx) {
    unsigned b = __float_as_uint(f);
    unsigned o = (b & 0x80000000u) ? ~b : (b | 0x80000000u);
    return ((u64)o << 32) | (unsigned)(~(unsigned)idx);
}

__device__ __forceinline__ void cp16(u32 dst, const void* src) {
    asm volatile("cp.async.cg.shared.global [%0], [%1], 16;" :: "r"(dst), "l"(src));
}
__device__ __forceinline__ u32 smem_u32(const void* p) {
    u32 a;
    asm("{ .reg .u64 t; cvta.to.shared.u64 t, %1; cvt.u32.u64 %0, t; }"
        : "=r"(a) : "l"(p));
    return a;
}

// ---------------------------------------------------------------------------
// Kernel 1: normalize queries, split to bf16 hi/lo, store padded [n][k]
// ---------------------------------------------------------------------------
__global__ void qprep_kernel(const float* __restrict__ q) {
    const int b = blockIdx.x;
    const int t = threadIdx.x;               // 256 threads x 4 floats
    float4 v = *(const float4*)(q + b * DIM + t * 4);
    float s = v.x * v.x + v.y * v.y + v.z * v.z + v.w * v.w;

    __shared__ float red[8];
    __shared__ float invn;
    #pragma unroll
    for (int o = 16; o; o >>= 1) s += __shfl_xor_sync(0xFFFFFFFFu, s, o);
    if ((t & 31) == 0) red[t >> 5] = s;
    __syncthreads();
    if (t == 0) {
        float tot = 0.f;
        #pragma unroll
        for (int i = 0; i < 8; i++) tot += red[i];
        invn = 1.f / (sqrtf(tot) + EPSV);
    }
    __syncthreads();
    float iv = invn;
    float x0 = v.x * iv, x1 = v.y * iv, x2 = v.z * iv, x3 = v.w * iv;

    u32 h0 = cvtpack(x1, x0), h1 = cvtpack(x3, x2);
    float e0 = x0 - lo2f(h0), e1 = x1 - hi2f(h0);
    float e2 = x2 - lo2f(h1), e3 = x3 - hi2f(h1);
    u32 l0 = cvtpack(e1, e0), l1 = cvtpack(e3, e2);

    char* dh = g_qB + b * QSTRIDE_B + t * 8;
    *(uint2*)dh            = make_uint2(h0, h1);
    *(uint2*)(dh + QMAT_B) = make_uint2(l0, l1);
    if (t < 4) {   // zero the 16-element pad (both matrices)
        *(uint2*)(g_qB + b * QSTRIDE_B + 2048 + t * 8)            = make_uint2(0, 0);
        *(uint2*)(g_qB + b * QSTRIDE_B + 2048 + t * 8 + QMAT_B)   = make_uint2(0, 0);
    }
}

// ---------------------------------------------------------------------------
// Kernel 2: bf16-split HMMA similarity. 1563 CTAs x 256 threads.
// ---------------------------------------------------------------------------
struct StepCtx {
    const float* rp[4];     // row pointers (lane col folded in)
    const char*  bh[2];     // B hi, per ntile (lane n folded in)
    const char*  bl[2];
};

__device__ __forceinline__ void step(int s, float4* bp, const StepCtx& cx,
                                     float d[2][2][4], float* nrm) {
    // ---- convert current chunk fp32 -> bf16 hi/lo fragments + norms ----
    u32 ah[2][4], al[2][4];
    #pragma unroll
    for (int m = 0; m < 2; m++) {
        float4 f = bp[2 * m], g = bp[2 * m + 1];
        nrm[2 * m]     += f.x * f.x + f.y * f.y + f.z * f.z + f.w * f.w;
        nrm[2 * m + 1] += g.x * g.x + g.y * g.y + g.z * g.z + g.w * g.w;
        u32 fh0 = cvtpack(f.y, f.x), fh1 = cvtpack(f.w, f.z);
        u32 gh0 = cvtpack(g.y, g.x), gh1 = cvtpack(g.w, g.z);
        ah[m][0] = fh0; ah[m][1] = gh0; ah[m][2] = fh1; ah[m][3] = gh1;
        float e0 = f.x - lo2f(fh0), e1 = f.y - hi2f(fh0);
        float e2 = f.z - lo2f(fh1), e3 = f.w - hi2f(fh1);
        float u0 = g.x - lo2f(gh0), u1 = g.y - hi2f(gh0);
        float u2 = g.z - lo2f(gh1), u3 = g.w - hi2f(gh1);
        al[m][0] = cvtpack(e1, e0); al[m][1] = cvtpack(u1, u0);
        al[m][2] = cvtpack(e3, e2); al[m][3] = cvtpack(u3, u2);
    }
    // ---- prefetch chunk s+2 into the same buffer ----
    if (s + 2 < NCHUNK) {
        #pragma unroll
        for (int i = 0; i < 4; i++)
            bp[i] = *(const float4*)(cx.rp[i] + (s + 2) * 16);
    }
    // ---- B fragments from smem (one LDS.64 per ntile per matrix) ----
    u32 bhf[2][2], blf[2][2];
    #pragma unroll
    for (int nt = 0; nt < 2; nt++) {
        uint2 vh = *(const uint2*)(cx.bh[nt] + s * 32);
        uint2 vl = *(const uint2*)(cx.bl[nt] + s * 32);
        bhf[nt][0] = vh.x; bhf[nt][1] = vh.y;
        blf[nt][0] = vl.x; blf[nt][1] = vl.y;
    }
    // ---- 12 MMAs: hi*hi + hi*lo + lo*hi, same accumulator ----
    #pragma unroll
    for (int m = 0; m < 2; m++)
        #pragma unroll
        for (int nt = 0; nt < 2; nt++) {
            mma16816(d[m][nt], ah[m], bhf[nt]);
            mma16816(d[m][nt], ah[m], blf[nt]);
            mma16816(d[m][nt], al[m], bhf[nt]);
        }
}

__global__ void __launch_bounds__(256, 2)
sim_kernel(const float* __restrict__ db) {
    extern __shared__ char smem[];
    const u32 sb = smem_u32(smem);
    const int t = threadIdx.x;
    const int w = t >> 5, lane = t & 31;
    const int rq = lane >> 2, c = lane & 3;
    const int rowBase = blockIdx.x * RB;

    // ---- copy queries (hi+lo) into smem via cp.async ----
    #pragma unroll
    for (int i = 0; i < 17; i++) {
        int ch = t + i * 256;
        if (ch < QTOT_B / 16)
            cp16(sb + (u32)ch * 16u, g_qB + (size_t)ch * 16);
    }
    asm volatile("cp.async.commit_group;");

    // ---- row pointers (clamped for tail CTA) ----
    StepCtx cx;
    int rloc[4];
    #pragma unroll
    for (int i = 0; i < 4; i++) {
        rloc[i] = w * 32 + rq + i * 8;
        int gr = rowBase + rloc[i];
        int grc = gr < NDB ? gr : NDB - 1;
        cx.rp[i] = db + (size_t)grc * DIM + c * 4;
    }
    cx.bh[0] = smem + rq * QSTRIDE_B + c * 8;
    cx.bh[1] = smem + (8 + rq) * QSTRIDE_B + c * 8;
    cx.bl[0] = cx.bh[0] + QMAT_B;
    cx.bl[1] = cx.bh[1] + QMAT_B;

    // preload chunks 0,1
    float4 buf[2][4];
    #pragma unroll
    for (int i = 0; i < 4; i++) {
        buf[0][i] = *(const float4*)(cx.rp[i]);
        buf[1][i] = *(const float4*)(cx.rp[i] + 16);
    }

    float d[2][2][4];
    #pragma unroll
    for (int m = 0; m < 2; m++)
        #pragma unroll
        for (int nt = 0; nt < 2; nt++)
            #pragma unroll
            for (int j = 0; j < 4; j++) d[m][nt][j] = 0.f;
    float nrm[4] = {0.f, 0.f, 0.f, 0.f};

    asm volatile("cp.async.wait_group 0;");
    __syncthreads();

    #pragma unroll 1
    for (int s2 = 0; s2 < NCHUNK; s2 += 2) {
        step(s2,     buf[0], cx, d, nrm);
        step(s2 + 1, buf[1], cx, d, nrm);
    }

    // ---- norms: reduce over the lane quad (same rq, c=0..3) ----
    float inv[4];
    #pragma unroll
    for (int j = 0; j < 4; j++) {
        float n = nrm[j];
        n += __shfl_xor_sync(0xFFFFFFFFu, n, 1);
        n += __shfl_xor_sync(0xFFFFFFFFu, n, 2);
        inv[j] = 1.f / (sqrtf(n) + EPSV);
    }
    bool valid[4];
    int  grow[4];
    #pragma unroll
    for (int j = 0; j < 4; j++) {
        grow[j] = rowBase + rloc[j];
        valid[j] = grow[j] < NDB;
    }

    // ---- per-lane 4 queries: local best/sum, reduce across lanes {c,c+4,...} ----
    u64*   skey = (u64*)(smem + QTOT_B);            // [16][8]
    float* ssum = (float*)(smem + QTOT_B + 1024);   // [16][8]
    #pragma unroll
    for (int nt = 0; nt < 2; nt++)
        #pragma unroll
        for (int j = 0; j < 2; j++) {
            int q = nt * 8 + 2 * c + j;
            float s0 = d[0][nt][j]     * inv[0];
            float s1 = d[0][nt][2 + j] * inv[1];
            float s2 = d[1][nt][j]     * inv[2];
            float s3 = d[1][nt][2 + j] * inv[3];
            u64 kb = 0ull; float sm = 0.f;
            if (valid[0]) { u64 k = pack_key(s0, grow[0]); if (k > kb) kb = k; sm += s0; }
            if (valid[1]) { u64 k = pack_key(s1, grow[1]); if (k > kb) kb = k; sm += s1; }
            if (valid[2]) { u64 k = pack_key(s2, grow[2]); if (k > kb) kb = k; sm += s2; }
            if (valid[3]) { u64 k = pack_key(s3, grow[3]); if (k > kb) kb = k; sm += s3; }
            #pragma unroll
            for (int o = 4; o <= 16; o <<= 1) {
                u64   ok = __shfl_xor_sync(0xFFFFFFFFu, kb, o);
                float os = __shfl_xor_sync(0xFFFFFFFFu, sm, o);
                if (ok > kb) kb = ok;
                sm += os;
            }
            if (rq == 0) { skey[q * 8 + w] = kb; ssum[q * 8 + w] = sm; }
        }
    __syncthreads();

    // ---- final: 128 threads reduce 8 warps per query ----
    if (t < 128) {
        int q = t >> 3, w2 = t & 7;
        u64 kb = skey[q * 8 + w2];
        float sm = ssum[q * 8 + w2];
        #pragma unroll
        for (int o = 4; o; o >>= 1) {
            u64   ok = __shfl_down_sync(0xFFFFFFFFu, kb, o, 8);
            float os = __shfl_down_sync(0xFFFFFFFFu, sm, o, 8);
            if (ok > kb) kb = ok;
            sm += os;
        }
        if (w2 == 0) {
            g_pkey[(size_t)blockIdx.x * NQ + q] = kb;
            g_psum[(size_t)blockIdx.x * NQ + q] = sm;
        }
    }
}

// ---------------------------------------------------------------------------
// Kernel 3: finalize
// ---------------------------------------------------------------------------
__global__ void finalize_kernel(const int* __restrict__ db_classes,
                                const int* __restrict__ y,
                                float* __restrict__ out) {
    const int t = threadIdx.x;        // 256
    const int q = t >> 4, sub = t & 15;

    u64 kb = 0ull; float sm = 0.f;
    for (int i = sub; i < NBLK; i += 16) {
        u64 k = g_pkey[(size_t)i * NQ + q];
        if (k > kb) kb = k;
        sm += g_psum[(size_t)i * NQ + q];
    }
    #pragma unroll
    for (int o = 8; o; o >>= 1) {
        u64   ok = __shfl_down_sync(0xFFFFFFFFu, kb, o, 16);
        float os = __shfl_down_sync(0xFFFFFFFFu, sm, o, 16);
        if (ok > kb) kb = ok;
        sm += os;
    }

    __shared__ u64   skey[NQ];
    __shared__ float ssum[NQ];
    __shared__ int   scls[NQ];
    if (sub == 0) { skey[q] = kb; ssum[q] = sm; }
    __syncthreads();

    if (t < NQ) {
        u64 k = skey[t];
        unsigned idx = ~((unsigned)k);
        unsigned o   = (unsigned)(k >> 32);
        unsigned fb  = (o & 0x80000000u) ? (o & 0x7FFFFFFFu) : ~o;
        float mx = __uint_as_float(fb);
        int cls = db_classes[idx];
        out[t]          = mx;
        out[NQ + t]     = ssum[t] / (float)NDB;
        out[2 * NQ + t] = (float)cls;
        scls[t] = cls;
    }
    __syncthreads();
    if (t == 0) {
        int cnt = 0;
        #pragma unroll
        for (int i = 0; i < NQ; i++) cnt += (scls[i] == y[i]) ? 1 : 0;
        out[3 * NQ] = (float)cnt / (float)NQ;
    }
}

// ---------------------------------------------------------------------------
// kernel_launch
// ---------------------------------------------------------------------------
extern "C" void kernel_launch(void* const* d_in, const int* in_sizes, int n_in,
                              void* d_out, int out_size) {
    const float* queries    = (const float*)d_in[0];
    const float* database   = (const float*)d_in[1];
    const int*   db_classes = (const int*)d_in[2];
    const int*   y          = (const int*)d_in[3];
    float* out = (float*)d_out;

    cudaFuncSetAttribute(sim_kernel,
                         cudaFuncAttributeMaxDynamicSharedMemorySize,
                         SMEM_TOTAL);

    qprep_kernel<<<NQ, 256>>>(queries);
    sim_kernel<<<NBLK, 256, SMEM_TOTAL>>>(database);
    finalize_kernel<<<1, 256>>>(db_classes, y, out);
}

// round 4
// speedup vs baseline: 1.7064x; 1.1349x over previous
#include <cuda_runtime.h>
#include <cuda_bf16.h>
#include <math.h>

// ---------------------------------------------------------------------------
// Problem constants
// ---------------------------------------------------------------------------
#define NQ      16
#define DIM     1024
#define NDB     400000
#define RB      256                       // rows per tile
#define NBLK    ((NDB + RB - 1) / RB)     // 1563 tiles
#define KC64    64                        // floats per stage per row
#define NSTG    (DIM / KC64)              // 16 stages per tile
#define EPSV    1e-8f
#define GRID    152

// Query smem: padded bf16 rows, stride 2080 B (conflict-free LDS.64)
#define QSTRIDE_B  2080
#define QMAT_B     (NQ * QSTRIDE_B)       // 33280
#define QTOT_B     (2 * QMAT_B)           // 66560
// DB stages: 2 x (256 rows x 256 B) with XOR-4 unit swizzle
#define STG_B      65536
#define OFF_STG0   QTOT_B
#define OFF_STG1   (OFF_STG0 + STG_B)
#define OFF_SCR    (OFF_STG1 + STG_B)     // skey 1024 | ssum 512 | tileSlot
#define SMEM_TOTAL (OFF_SCR + 2048)       // 199680 B

typedef unsigned int       u32;
typedef unsigned long long u64;

// ---------------------------------------------------------------------------
// Device scratch
// ---------------------------------------------------------------------------
__device__ __align__(16) char g_qB[QTOT_B];
__device__ u64      g_pkey[NBLK * NQ];
__device__ float    g_psum[NBLK * NQ];
__device__ unsigned g_ctr;

// ---------------------------------------------------------------------------
// Helpers
// ---------------------------------------------------------------------------
__device__ __forceinline__ u32 cvtpack(float hi, float lo) {
    __nv_bfloat162 h = __floats2bfloat162_rn(lo, hi);
    return *(u32*)&h;
}
__device__ __forceinline__ float lo2f(u32 p) { return __uint_as_float(p << 16); }
__device__ __forceinline__ float hi2f(u32 p) { return __uint_as_float(p & 0xFFFF0000u); }

__device__ __forceinline__ void mma16816(float* d, const u32* a, const u32* b) {
    asm volatile(
        "mma.sync.aligned.m16n8k16.row.col.f32.bf16.bf16.f32 "
        "{%0,%1,%2,%3}, {%4,%5,%6,%7}, {%8,%9}, {%0,%1,%2,%3};"
        : "+f"(d[0]), "+f"(d[1]), "+f"(d[2]), "+f"(d[3])
        : "r"(a[0]), "r"(a[1]), "r"(a[2]), "r"(a[3]), "r"(b[0]), "r"(b[1]));
}
__device__ __forceinline__ u64 pack_key(float f, int idx) {
    unsigned b = __float_as_uint(f);
    unsigned o = (b & 0x80000000u) ? ~b : (b | 0x80000000u);
    return ((u64)o << 32) | (unsigned)(~(unsigned)idx);
}
__device__ __forceinline__ void cp16(u32 dst, const void* src) {
    asm volatile("cp.async.cg.shared.global [%0], [%1], 16;" :: "r"(dst), "l"(src));
}
__device__ __forceinline__ u32 smem_u32(const void* p) {
    u32 a;
    asm("{ .reg .u64 t; cvta.to.shared.u64 t, %1; cvt.u32.u64 %0, t; }"
        : "=r"(a) : "l"(p));
    return a;
}

// ---------------------------------------------------------------------------
// Kernel 1: normalize queries, bf16 hi/lo split, padded store; reset counter
// ---------------------------------------------------------------------------
__global__ void qprep_kernel(const float* __restrict__ q) {
    const int b = blockIdx.x;
    const int t = threadIdx.x;               // 256 threads x 4 floats
    if (b == 0 && t == 0) g_ctr = 0;

    float4 v = *(const float4*)(q + b * DIM + t * 4);
    float s = v.x * v.x + v.y * v.y + v.z * v.z + v.w * v.w;

    __shared__ float red[8];
    __shared__ float invn;
    #pragma unroll
    for (int o = 16; o; o >>= 1) s += __shfl_xor_sync(0xFFFFFFFFu, s, o);
    if ((t & 31) == 0) red[t >> 5] = s;
    __syncthreads();
    if (t == 0) {
        float tot = 0.f;
        #pragma unroll
        for (int i = 0; i < 8; i++) tot += red[i];
        invn = 1.f / (sqrtf(tot) + EPSV);
    }
    __syncthreads();
    float iv = invn;
    float x0 = v.x * iv, x1 = v.y * iv, x2 = v.z * iv, x3 = v.w * iv;

    u32 h0 = cvtpack(x1, x0), h1 = cvtpack(x3, x2);
    float e0 = x0 - lo2f(h0), e1 = x1 - hi2f(h0);
    float e2 = x2 - lo2f(h1), e3 = x3 - hi2f(h1);
    u32 l0 = cvtpack(e1, e0), l1 = cvtpack(e3, e2);

    char* dh = g_qB + b * QSTRIDE_B + t * 8;
    *(uint2*)dh            = make_uint2(h0, h1);
    *(uint2*)(dh + QMAT_B) = make_uint2(l0, l1);
    if (t < 4) {
        *(uint2*)(g_qB + b * QSTRIDE_B + 2048 + t * 8)          = make_uint2(0, 0);
        *(uint2*)(g_qB + b * QSTRIDE_B + 2048 + t * 8 + QMAT_B) = make_uint2(0, 0);
    }
}

// ---------------------------------------------------------------------------
// Stage loader: fully-coalesced 256B-per-row requests into swizzled smem
// ---------------------------------------------------------------------------
__device__ __forceinline__ void issue_stage(const float* __restrict__ db, u32 sb,
                                            int tile, int s, int t, bool valid) {
    if (valid) {
        const u32 base = sb + ((s & 1) ? OFF_STG1 : OFF_STG0);
        const int rowBase = tile * RB;
        #pragma unroll
        for (int i = 0; i < 16; i++) {
            int idx = i * 256 + t;           // 16 consecutive lanes = one 256B row seg
            int row = idx >> 4, u = idx & 15;
            int up = u ^ ((row & 1) << 2);
            long long gr = rowBase + row;
            if (gr > NDB - 1) gr = NDB - 1;
            const float* src = db + gr * (long long)DIM + s * KC64 + u * 4;
            cp16(base + (u32)(row * 256 + up * 16), src);
        }
    }
    asm volatile("cp.async.commit_group;");
}

// ---------------------------------------------------------------------------
// Kernel 2: persistent bf16-split HMMA similarity
// ---------------------------------------------------------------------------
__global__ void __launch_bounds__(256, 1)
sim_kernel(const float* __restrict__ db) {
    extern __shared__ char smem[];
    const u32 sb = smem_u32(smem);
    const int t = threadIdx.x;
    const int w = t >> 5, lane = t & 31;
    const int rq = lane >> 2, c = lane & 3;
    const u32 xr = (u32)((rq & 1) << 2);

    u64*   skey = (u64*)(smem + OFF_SCR);
    float* ssum = (float*)(smem + OFF_SCR + 1024);
    volatile int* tileSlot = (volatile int*)(smem + OFF_SCR + 1792);

    // ---- Q copy (its group drains with the first wait) ----
    #pragma unroll
    for (int i = 0; i < 17; i++) {
        int ch = t + i * 256;
        if (ch < QTOT_B / 16)
            cp16(sb + (u32)ch * 16u, g_qB + (size_t)ch * 16);
    }
    asm volatile("cp.async.commit_group;");

    // ---- per-lane constant addressing ----
    const char* bh[2];
    const char* bl[2];
    bh[0] = smem + rq * QSTRIDE_B + c * 8;
    bh[1] = bh[0] + 8 * QSTRIDE_B;
    bl[0] = bh[0] + QMAT_B;
    bl[1] = bh[1] + QMAT_B;
    int rloc[4];
    u32 rowoff[4];
    #pragma unroll
    for (int i = 0; i < 4; i++) {
        rloc[i] = w * 32 + rq + i * 8;
        rowoff[i] = (u32)rloc[i] * 256u;
    }

    // ---- first tile + two-stage prologue ----
    if (t == 0) tileSlot[0] = (int)atomicAdd(&g_ctr, 1u);
    __syncthreads();
    int tile = tileSlot[0];
    if (tile >= NBLK) {
        asm volatile("cp.async.wait_group 0;");
        return;
    }
    issue_stage(db, sb, tile, 0, t, true);
    issue_stage(db, sb, tile, 1, t, true);

    while (tile < NBLK) {
        float d[2][2][4];
        float nrm[4] = {0.f, 0.f, 0.f, 0.f};
        #pragma unroll
        for (int m = 0; m < 2; m++)
            #pragma unroll
            for (int nt = 0; nt < 2; nt++)
                #pragma unroll
                for (int j = 0; j < 4; j++) d[m][nt][j] = 0.f;

        int next = 0x7FFFFFFF;
        #pragma unroll 1
        for (int s = 0; s < NSTG; s++) {
            asm volatile("cp.async.wait_group 1;");
            __syncthreads();
            const char* A = smem + ((s & 1) ? OFF_STG1 : OFF_STG0);

            #pragma unroll
            for (int j = 0; j < 4; j++) {
                const int ch = s * 4 + j;
                const u32 uoff = (u32)((((u32)(j * 4 + c)) ^ xr) * 16u);
                float4 av[4];
                #pragma unroll
                for (int i = 0; i < 4; i++)
                    av[i] = *(const float4*)(A + rowoff[i] + uoff);

                u32 ah[2][4], al[2][4];
                #pragma unroll
                for (int m = 0; m < 2; m++) {
                    float4 f = av[2 * m], g = av[2 * m + 1];
                    nrm[2 * m]     += f.x * f.x + f.y * f.y + f.z * f.z + f.w * f.w;
                    nrm[2 * m + 1] += g.x * g.x + g.y * g.y + g.z * g.z + g.w * g.w;
                    u32 fh0 = cvtpack(f.y, f.x), fh1 = cvtpack(f.w, f.z);
                    u32 gh0 = cvtpack(g.y, g.x), gh1 = cvtpack(g.w, g.z);
                    ah[m][0] = fh0; ah[m][1] = gh0; ah[m][2] = fh1; ah[m][3] = gh1;
                    float e0 = f.x - lo2f(fh0), e1 = f.y - hi2f(fh0);
                    float e2 = f.z - lo2f(fh1), e3 = f.w - hi2f(fh1);
                    float u0 = g.x - lo2f(gh0), u1 = g.y - hi2f(gh0);
                    float u2 = g.z - lo2f(gh1), u3 = g.w - hi2f(gh1);
                    al[m][0] = cvtpack(e1, e0); al[m][1] = cvtpack(u1, u0);
                    al[m][2] = cvtpack(e3, e2); al[m][3] = cvtpack(u3, u2);
                }
                u32 bhf[2][2], blf[2][2];
                #pragma unroll
                for (int nt = 0; nt < 2; nt++) {
                    uint2 vh = *(const uint2*)(bh[nt] + ch * 32);
                    uint2 vl = *(const uint2*)(bl[nt] + ch * 32);
                    bhf[nt][0] = vh.x; bhf[nt][1] = vh.y;
                    blf[nt][0] = vl.x; blf[nt][1] = vl.y;
                }
                #pragma unroll
                for (int m = 0; m < 2; m++)
                    #pragma unroll
                    for (int nt = 0; nt < 2; nt++) {
                        mma16816(d[m][nt], ah[m], bhf[nt]);
                        mma16816(d[m][nt], ah[m], blf[nt]);
                        mma16816(d[m][nt], al[m], bhf[nt]);
                    }
            }

            if (s == NSTG - 3 && t == 0)
                tileSlot[0] = (int)atomicAdd(&g_ctr, 1u);
            __syncthreads();

            if (s < NSTG - 2) {
                issue_stage(db, sb, tile, s + 2, t, true);
            } else if (s == NSTG - 2) {
                next = tileSlot[0];
                issue_stage(db, sb, next, 0, t, next < NBLK);
            } else {
                issue_stage(db, sb, next, 1, t, next < NBLK);
            }
        }

        // ---- epilogue (overlaps next tile's stage loads) ----
        float inv[4];
        #pragma unroll
        for (int j = 0; j < 4; j++) {
            float n = nrm[j];
            n += __shfl_xor_sync(0xFFFFFFFFu, n, 1);
            n += __shfl_xor_sync(0xFFFFFFFFu, n, 2);
            inv[j] = 1.f / (sqrtf(n) + EPSV);
        }
        int  grow[4];
        bool valid[4];
        #pragma unroll
        for (int j = 0; j < 4; j++) {
            grow[j] = tile * RB + rloc[j];
            valid[j] = grow[j] < NDB;
        }
        #pragma unroll
        for (int nt = 0; nt < 2; nt++)
            #pragma unroll
            for (int j = 0; j < 2; j++) {
                int q = nt * 8 + 2 * c + j;
                float s0 = d[0][nt][j]     * inv[0];
                float s1 = d[0][nt][2 + j] * inv[1];
                float s2 = d[1][nt][j]     * inv[2];
                float s3 = d[1][nt][2 + j] * inv[3];
                u64 kb = 0ull; float sm = 0.f;
                if (valid[0]) { u64 k = pack_key(s0, grow[0]); if (k > kb) kb = k; sm += s0; }
                if (valid[1]) { u64 k = pack_key(s1, grow[1]); if (k > kb) kb = k; sm += s1; }
                if (valid[2]) { u64 k = pack_key(s2, grow[2]); if (k > kb) kb = k; sm += s2; }
                if (valid[3]) { u64 k = pack_key(s3, grow[3]); if (k > kb) kb = k; sm += s3; }
                #pragma unroll
                for (int o = 4; o <= 16; o <<= 1) {
                    u64   ok = __shfl_xor_sync(0xFFFFFFFFu, kb, o);
                    float os = __shfl_xor_sync(0xFFFFFFFFu, sm, o);
                    if (ok > kb) kb = ok;
                    sm += os;
                }
                if (rq == 0) { skey[q * 8 + w] = kb; ssum[q * 8 + w] = sm; }
            }
        __syncthreads();
        if (t < 128) {
            int q = t >> 3, w2 = t & 7;
            u64 kb = skey[q * 8 + w2];
            float sm = ssum[q * 8 + w2];
            #pragma unroll
            for (int o = 4; o; o >>= 1) {
                u64   ok = __shfl_down_sync(0xFFFFFFFFu, kb, o, 8);
                float os = __shfl_down_sync(0xFFFFFFFFu, sm, o, 8);
                if (ok > kb) kb = ok;
                sm += os;
            }
            if (w2 == 0) {
                g_pkey[(size_t)tile * NQ + q] = kb;
                g_psum[(size_t)tile * NQ + q] = sm;
            }
        }
        __syncthreads();
        tile = next;
    }
    asm volatile("cp.async.wait_group 0;");
}

// ---------------------------------------------------------------------------
// Kernel 3: finalize
// ---------------------------------------------------------------------------
__global__ void finalize_kernel(const int* __restrict__ db_classes,
                                const int* __restrict__ y,
                                float* __restrict__ out) {
    const int t = threadIdx.x;        // 256
    const int q = t >> 4, sub = t & 15;

    u64 kb = 0ull; float sm = 0.f;
    for (int i = sub; i < NBLK; i += 16) {
        u64 k = g_pkey[(size_t)i * NQ + q];
        if (k > kb) kb = k;
        sm += g_psum[(size_t)i * NQ + q];
    }
    #pragma unroll
    for (int o = 8; o; o >>= 1) {
        u64   ok = __shfl_down_sync(0xFFFFFFFFu, kb, o, 16);
        float os = __shfl_down_sync(0xFFFFFFFFu, sm, o, 16);
        if (ok > kb) kb = ok;
        sm += os;
    }

    __shared__ u64   skey[NQ];
    __shared__ float ssum[NQ];
    __shared__ int   scls[NQ];
    if (sub == 0) { skey[q] = kb; ssum[q] = sm; }
    __syncthreads();

    if (t < NQ) {
        u64 k = skey[t];
        unsigned idx = ~((unsigned)k);
        unsigned o   = (unsigned)(k >> 32);
        unsigned fb  = (o & 0x80000000u) ? (o & 0x7FFFFFFFu) : ~o;
        float mx = __uint_as_float(fb);
        int cls = db_classes[idx];
        out[t]          = mx;
        out[NQ + t]     = ssum[t] / (float)NDB;
        out[2 * NQ + t] = (float)cls;
        scls[t] = cls;
    }
    __syncthreads();
    if (t == 0) {
        int cnt = 0;
        #pragma unroll
        for (int i = 0; i < NQ; i++) cnt += (scls[i] == y[i]) ? 1 : 0;
        out[3 * NQ] = (float)cnt / (float)NQ;
    }
}

// ---------------------------------------------------------------------------
// kernel_launch
// ---------------------------------------------------------------------------
extern "C" void kernel_launch(void* const* d_in, const int* in_sizes, int n_in,
                              void* d_out, int out_size) {
    const float* queries    = (const float*)d_in[0];
    const float* database   = (const float*)d_in[1];
    const int*   db_classes = (const int*)d_in[2];
    const int*   y          = (const int*)d_in[3];
    float* out = (float*)d_out;

    cudaFuncSetAttribute(sim_kernel,
                         cudaFuncAttributeMaxDynamicSharedMemorySize,
                         SMEM_TOTAL);

    qprep_kernel<<<NQ, 256>>>(queries);
    sim_kernel<<<GRID, 256, SMEM_TOTAL>>>(database);
    finalize_kernel<<<1, 256>>>(db_classes, y, out);
}